// round 3
// baseline (speedup 1.0000x reference)
#include <cuda_runtime.h>
#include <cstdint>

#define HSZ   512
#define ISZ   256
#define BSZ   64
#define NBLK  128
#define NTHR  256
#define WHD_STR 1032   // 1024 dup floats + 8 pad
#define WID_STR 520    // 512 dup floats + 8 pad
#define EPSBN 1e-5f

// smem layout (floats)
#define OFF_WHD  0
#define OFF_WID  (OFF_WHD + 16*WHD_STR)        // 16512
#define OFF_ST   (OFF_WID + 16*WID_STR)        // +8320
#define OFF_SG   (OFF_ST + 3*4096)             // +12288 (triple buffer)
#define OFF_CST  (OFF_SG + 16*64)              // +1024
#define SMEM_FLOATS (OFF_CST + 96)
#define SMEM_BYTES  (SMEM_FLOATS*4)            // ~152.9 KB

__device__ float g_h[2][HSZ*BSZ];              // double-buffered hidden state
__device__ unsigned g_arrive;
__device__ unsigned g_release;

typedef unsigned long long ull;

__device__ __forceinline__ void unpack2(ull v, float &lo, float &hi){
    asm("mov.b64 {%0, %1}, %2;" : "=f"(lo), "=f"(hi) : "l"(v));
}
__device__ __forceinline__ void ffma2(ull &acc, ull a, ull b){
    asm("fma.rn.f32x2 %0, %1, %2, %0;" : "+l"(acc) : "l"(a), "l"(b));
}
__device__ __forceinline__ void cp16(uint32_t dst, const void* src){
    asm volatile("cp.async.cg.shared.global [%0], [%1], 16;" :: "r"(dst), "l"(src));
}
__device__ __forceinline__ float sigm(float x){
    return 1.0f / (1.0f + __expf(-x));
}

// one 64-k slice: thread does 1 gate-row x 4 batch-cols (2 f32x2 accumulators)
// wd: duplicated weights (pairs), st: staged h/x [k][64]
__device__ __forceinline__ void gemm_chunk1(const float* __restrict__ st,
                                            const float* __restrict__ wd,
                                            int c0, ull &a0, ull &a1)
{
    #pragma unroll
    for (int kk = 0; kk < 64; kk += 4){
        ulonglong2 wp = *(const ulonglong2*)(wd + kk*2);      // (w[k],w[k]),(w[k+1],w[k+1])
        ulonglong2 wq = *(const ulonglong2*)(wd + kk*2 + 4);  // (w[k+2],..),(w[k+3],..)
        ulonglong2 h0 = *(const ulonglong2*)(st + (kk+0)*64 + c0);
        ulonglong2 h1 = *(const ulonglong2*)(st + (kk+1)*64 + c0);
        ulonglong2 h2 = *(const ulonglong2*)(st + (kk+2)*64 + c0);
        ulonglong2 h3 = *(const ulonglong2*)(st + (kk+3)*64 + c0);
        ffma2(a0, wp.x, h0.x); ffma2(a1, wp.x, h0.y);
        ffma2(a0, wp.y, h1.x); ffma2(a1, wp.y, h1.y);
        ffma2(a0, wq.x, h2.x); ffma2(a1, wq.x, h2.y);
        ffma2(a0, wq.y, h3.x); ffma2(a1, wq.y, h3.y);
    }
}

extern "C" __global__ void __launch_bounds__(NTHR, 1)
lstm_bn_kernel(const float* __restrict__ x,
               const float* __restrict__ Wih,
               const float* __restrict__ Whh,
               const float* __restrict__ bias,
               const float* __restrict__ gIH, const float* __restrict__ bIH,
               const float* __restrict__ gHH, const float* __restrict__ bHH,
               const float* __restrict__ gC,  const float* __restrict__ bC,
               float* __restrict__ out, int T)
{
    extern __shared__ float sm[];
    float* whd    = sm + OFF_WHD;
    float* wid    = sm + OFF_WID;
    float* stage  = sm + OFF_ST;
    float* sg     = sm + OFF_SG;
    float* ghh_s  = sm + OFF_CST;       // 16
    float* bhh_s  = ghh_s + 16;
    float* gih_s  = bhh_s + 16;
    float* bih_s  = gih_s + 16;
    float* bias_s = bih_s + 16;
    float* gc_s   = bias_s + 16;        // 4
    float* bc_s   = gc_s + 4;           // 4

    const int tid = threadIdx.x;
    const int blk = blockIdx.x;
    const int ct  = tid & 15;           // batch col group 0..15
    const int rt  = tid >> 4;           // gate row 0..15
    const int c0  = ct * 4;

    // ---- preload weights, DUPLICATED (each value twice, adjacent)
    // block owns gate rows l=0..15 -> global row (l>>2)*512 + blk*4 + (l&3)
    for (int idx = tid; idx < 16*HSZ; idx += NTHR){
        int l = idx >> 9, k = idx & 511;
        int grow = (l >> 2) * HSZ + blk*4 + (l & 3);
        float v = Whh[(size_t)grow * HSZ + k];
        whd[l*WHD_STR + 2*k]     = v;
        whd[l*WHD_STR + 2*k + 1] = v;
    }
    for (int idx = tid; idx < 16*ISZ; idx += NTHR){
        int l = idx >> 8, k = idx & 255;
        int grow = (l >> 2) * HSZ + blk*4 + (l & 3);
        float v = Wih[(size_t)grow * ISZ + k];
        wid[l*WID_STR + 2*k]     = v;
        wid[l*WID_STR + 2*k + 1] = v;
    }
    if (tid < 16){
        int grow = (tid >> 2) * HSZ + blk*4 + (tid & 3);
        ghh_s[tid] = gHH[grow]; bhh_s[tid] = bHH[grow];
        gih_s[tid] = gIH[grow]; bih_s[tid] = bIH[grow];
        bias_s[tid] = bias[grow];
    }
    if (tid < 4){ gc_s[tid] = gC[blk*4 + tid]; bc_s[tid] = bC[blk*4 + tid]; }

    // ---- zero h buffer 0 (this block's slice: 256 floats)
    g_h[0][blk * NTHR + tid] = 0.f;
    __syncthreads();

    unsigned gen0 = 0, my_gen = 0;
    if (tid == 0) gen0 = *((volatile unsigned*)&g_release);

    auto gridsync = [&](){
        __syncthreads();
        if (tid == 0){
            my_gen++;
            __threadfence();
            unsigned a = atomicAdd(&g_arrive, 1u);
            if (a == (unsigned)(NBLK - 1)){
                atomicExch(&g_arrive, 0u);
                __threadfence();
                atomicAdd(&g_release, 1u);
            } else {
                while ( (*((volatile unsigned*)&g_release)) - gen0 < my_gen ) { }
            }
        }
        __syncthreads();
    };

    gridsync();   // h buffer zeroed everywhere before step 0

    const uint32_t stBase = (uint32_t)__cvta_generic_to_shared(stage);
    const float inv64 = 1.0f / 64.0f;
    float creg0 = 0.f, creg1 = 0.f;     // cell state rows (warps 0-3 only)
    const int wwarp = tid >> 5;         // warp id
    const int lane  = tid & 31;

    for (int t = 0; t < T; t++){
        const float* hrd = g_h[t & 1];
        float*       hwr = g_h[(t + 1) & 1];
        const float* xt  = x + (size_t)t * (ISZ*BSZ);

        ull aA0 = 0, aA1 = 0;   // W_hh @ h
        ull aB0 = 0, aB1 = 0;   // W_ih @ x_t

        // prefetch chunk 0 (h, k=0..63) into buf 0
        {
            uint32_t d = stBase;
            #pragma unroll
            for (int i = 0; i < 4; i++)
                cp16(d + (tid + i*256)*16, hrd + (tid + i*256)*4);
            asm volatile("cp.async.commit_group;");
        }

        for (int ci = 0; ci < 12; ci++){
            if (ci < 11){
                int cn = ci + 1;
                const float* src = (cn < 8) ? (hrd + cn*4096) : (xt + (cn - 8)*4096);
                uint32_t d = stBase + (uint32_t)((cn % 3) * 4096) * 4u;
                #pragma unroll
                for (int i = 0; i < 4; i++)
                    cp16(d + (tid + i*256)*16, src + (tid + i*256)*4);
                asm volatile("cp.async.commit_group;");
                asm volatile("cp.async.wait_group 1;");
            } else {
                asm volatile("cp.async.wait_group 0;");
            }
            __syncthreads();   // triple buffer: single barrier per chunk

            const float* st = stage + (ci % 3) * 4096;
            if (ci < 8)
                gemm_chunk1(st, whd + rt*WHD_STR + ci*128,       c0, aA0, aA1);
            else
                gemm_chunk1(st, wid + rt*WID_STR + (ci - 8)*128, c0, aB0, aB1);
        }

        // ---- phase A: per-gate-row batchnorm; thread owns row rt, cols c0..c0+3
        {
            float vA[4], vB[4];
            unpack2(aA0, vA[0], vA[1]); unpack2(aA1, vA[2], vA[3]);
            unpack2(aB0, vB[0], vB[1]); unpack2(aB1, vB[2], vB[3]);

            float sA = vA[0]+vA[1]+vA[2]+vA[3];
            float qA = vA[0]*vA[0]+vA[1]*vA[1]+vA[2]*vA[2]+vA[3]*vA[3];
            float sB = vB[0]+vB[1]+vB[2]+vB[3];
            float qB = vB[0]*vB[0]+vB[1]*vB[1]+vB[2]*vB[2]+vB[3]*vB[3];
            #pragma unroll
            for (int off = 1; off < 16; off <<= 1){
                sA += __shfl_xor_sync(0xffffffffu, sA, off);
                qA += __shfl_xor_sync(0xffffffffu, qA, off);
                sB += __shfl_xor_sync(0xffffffffu, sB, off);
                qB += __shfl_xor_sync(0xffffffffu, qB, off);
            }
            float muA = sA*inv64, muB = sB*inv64;
            float rsA = rsqrtf(qA*inv64 - muA*muA + EPSBN);
            float rsB = rsqrtf(qB*inv64 - muB*muB + EPSBN);
            float ga = ghh_s[rt]*rsA, gb = gih_s[rt]*rsB;
            float cadd = bhh_s[rt] + bih_s[rt] + bias_s[rt] - muA*ga - muB*gb;
            #pragma unroll
            for (int j = 0; j < 4; j++)
                sg[rt*64 + c0 + j] = fmaf(vA[j], ga, fmaf(vB[j], gb, cadd));
        }
        __syncthreads();

        // ---- phase B: gates + cell + c-BN + h  (warps 0-3; warp w owns h-row blk*4+w)
        if (wwarp < 4){
            float iv0 = sg[( 0 + wwarp)*64 + lane], iv1 = sg[( 0 + wwarp)*64 + lane + 32];
            float fv0 = sg[( 4 + wwarp)*64 + lane], fv1 = sg[( 4 + wwarp)*64 + lane + 32];
            float gv0 = sg[( 8 + wwarp)*64 + lane], gv1 = sg[( 8 + wwarp)*64 + lane + 32];
            float ov0 = sg[(12 + wwarp)*64 + lane], ov1 = sg[(12 + wwarp)*64 + lane + 32];

            creg0 = sigm(fv0)*creg0 + sigm(iv0)*tanhf(gv0);
            creg1 = sigm(fv1)*creg1 + sigm(iv1)*tanhf(gv1);

            float sc = creg0 + creg1;
            float qc = creg0*creg0 + creg1*creg1;
            #pragma unroll
            for (int off = 16; off >= 1; off >>= 1){
                sc += __shfl_xor_sync(0xffffffffu, sc, off);
                qc += __shfl_xor_sync(0xffffffffu, qc, off);
            }
            float mu = sc*inv64;
            float rs = rsqrtf(qc*inv64 - mu*mu + EPSBN);
            float gcv = gc_s[wwarp]*rs;
            float bcv = bc_s[wwarp] - mu*gcv;
            float h0v = sigm(ov0) * tanhf(fmaf(creg0, gcv, bcv));
            float h1v = sigm(ov1) * tanhf(fmaf(creg1, gcv, bcv));

            int rowg = blk*4 + wwarp;
            hwr[rowg*64 + lane]      = h0v;
            hwr[rowg*64 + lane + 32] = h1v;
            float* op = out + (size_t)t * (HSZ*BSZ) + rowg*64;
            op[lane]      = h0v;
            op[lane + 32] = h1v;
        }

        gridsync();   // h visible chip-wide before next step's loads
    }
}

extern "C" void kernel_launch(void* const* d_in, const int* in_sizes, int n_in,
                              void* d_out, int out_size)
{
    const float* x    = (const float*)d_in[0];
    const float* Wih  = (const float*)d_in[1];
    const float* Whh  = (const float*)d_in[2];
    const float* bias = (const float*)d_in[3];
    const float* gIH  = (const float*)d_in[4];
    const float* bIH  = (const float*)d_in[5];
    const float* gHH  = (const float*)d_in[6];
    const float* bHH  = (const float*)d_in[7];
    const float* gC   = (const float*)d_in[8];
    const float* bC   = (const float*)d_in[9];
    float* out = (float*)d_out;

    int T = in_sizes[0] / (ISZ * BSZ);   // 2048

    cudaFuncSetAttribute(lstm_bn_kernel,
                         cudaFuncAttributeMaxDynamicSharedMemorySize, SMEM_BYTES);
    lstm_bn_kernel<<<NBLK, NTHR, SMEM_BYTES>>>(x, Wih, Whh, bias,
                                               gIH, bIH, gHH, bHH, gC, bC,
                                               out, T);
}